// round 1
// baseline (speedup 1.0000x reference)
#include <cuda_runtime.h>

// Row 0..2 of the 4x4 SE3 matrix, each as (R_i0, R_i1, R_i2, t_i).
// Row 3 is [0,0,0,1] implicitly (output row 3 = input row 3).
__device__ float4 g_Mrows[3];

// One-thread kernel: build exp([w]x, v; theta) 4x4 matrix.
__global__ void se3_build_matrix(const float* __restrict__ w,
                                 const float* __restrict__ v,
                                 const float* __restrict__ theta_p) {
    if (threadIdx.x == 0 && blockIdx.x == 0) {
        const float wx = w[0], wy = w[1], wz = w[2];
        const float vx = v[0], vy = v[1], vz = v[2];
        const float th = theta_p[0];
        const float s = sinf(th);
        const float c = cosf(th);
        const float a = 1.0f - c;      // matches jax fp32: (1 - cos)
        const float b = th - s;        // matches jax fp32: (theta - sin)

        // K = skew(w)
        float K[3][3] = { {0.f, -wz,  wy},
                          { wz, 0.f, -wx},
                          {-wy,  wx, 0.f} };
        // KK = K @ K
        float KK[3][3];
        #pragma unroll
        for (int i = 0; i < 3; i++)
            #pragma unroll
            for (int j = 0; j < 3; j++)
                KK[i][j] = K[i][0]*K[0][j] + K[i][1]*K[1][j] + K[i][2]*K[2][j];

        float R[3][3], V[3][3];
        #pragma unroll
        for (int i = 0; i < 3; i++)
            #pragma unroll
            for (int j = 0; j < 3; j++) {
                const float I = (i == j) ? 1.0f : 0.0f;
                R[i][j] = I + s * K[i][j] + a * KK[i][j];
                V[i][j] = I * th + a * K[i][j] + b * KK[i][j];
            }

        // t = V @ v
        float t[3];
        #pragma unroll
        for (int i = 0; i < 3; i++)
            t[i] = V[i][0]*vx + V[i][1]*vy + V[i][2]*vz;

        g_Mrows[0] = make_float4(R[0][0], R[0][1], R[0][2], t[0]);
        g_Mrows[1] = make_float4(R[1][0], R[1][1], R[1][2], t[1]);
        g_Mrows[2] = make_float4(R[2][0], R[2][1], R[2][2], t[2]);
    }
}

// Streaming transform: out[r][i] = sum_j M[r][j] * x[j][i], row 3 = copy.
// x and out are [4, N] row-major; processed as float4 columns (n4 = N/4).
__global__ void __launch_bounds__(256)
se3_transform(const float4* __restrict__ x, float4* __restrict__ out, int n4) {
    const int i = blockIdx.x * blockDim.x + threadIdx.x;
    if (i >= n4) return;

    const float4 m0 = g_Mrows[0];
    const float4 m1 = g_Mrows[1];
    const float4 m2 = g_Mrows[2];

    const float4 x0 = x[i];
    const float4 x1 = x[i + (size_t)n4];
    const float4 x2 = x[i + 2 * (size_t)n4];
    const float4 x3 = x[i + 3 * (size_t)n4];

    float4 r0, r1, r2;
    r0.x = m0.x*x0.x + m0.y*x1.x + m0.z*x2.x + m0.w*x3.x;
    r0.y = m0.x*x0.y + m0.y*x1.y + m0.z*x2.y + m0.w*x3.y;
    r0.z = m0.x*x0.z + m0.y*x1.z + m0.z*x2.z + m0.w*x3.z;
    r0.w = m0.x*x0.w + m0.y*x1.w + m0.z*x2.w + m0.w*x3.w;

    r1.x = m1.x*x0.x + m1.y*x1.x + m1.z*x2.x + m1.w*x3.x;
    r1.y = m1.x*x0.y + m1.y*x1.y + m1.z*x2.y + m1.w*x3.y;
    r1.z = m1.x*x0.z + m1.y*x1.z + m1.z*x2.z + m1.w*x3.z;
    r1.w = m1.x*x0.w + m1.y*x1.w + m1.z*x2.w + m1.w*x3.w;

    r2.x = m2.x*x0.x + m2.y*x1.x + m2.z*x2.x + m2.w*x3.x;
    r2.y = m2.x*x0.y + m2.y*x1.y + m2.z*x2.y + m2.w*x3.y;
    r2.z = m2.x*x0.z + m2.y*x1.z + m2.z*x2.z + m2.w*x3.z;
    r2.w = m2.x*x0.w + m2.y*x1.w + m2.z*x2.w + m2.w*x3.w;

    out[i]                   = r0;
    out[i + (size_t)n4]      = r1;
    out[i + 2 * (size_t)n4]  = r2;
    out[i + 3 * (size_t)n4]  = x3;   // bottom row of M is [0,0,0,1]
}

extern "C" void kernel_launch(void* const* d_in, const int* in_sizes, int n_in,
                              void* d_out, int out_size) {
    const float* x     = (const float*)d_in[0];   // [4, N]
    const float* w     = (const float*)d_in[1];   // [3]
    const float* v     = (const float*)d_in[2];   // [3]
    const float* theta = (const float*)d_in[3];   // scalar

    const int N  = in_sizes[0] / 4;   // columns
    const int n4 = N / 4;             // float4 columns per row

    se3_build_matrix<<<1, 32>>>(w, v, theta);

    const int threads = 256;
    const int blocks  = (n4 + threads - 1) / threads;
    se3_transform<<<blocks, threads>>>((const float4*)x, (float4*)d_out, n4);
}